// round 7
// baseline (speedup 1.0000x reference)
#include <cuda_runtime.h>
#include <cstdint>

// out[b, p*20+x, q*20+y] = (x!=y && p!=q) ? P[x,p]+Q[x,q]+Q[y,p]+P[y,q] : 0
//                          + (p==q && x==y) ? Mn[x,p] : 0
// P = F1 @ relu(L1) @ F2^T, Q = F1 @ relu(L2) @ F2^T, Mn = U1 @ U2^T (per batch)
//
// compute_kernel: grid 256, 512 threads, 2 CTAs/SM (8 warps/SMSP). Thread t
//   owns ONE column: t<256 -> L1 col t (T1), t>=256 -> L2 col t-256 (T2).
//   Depth-8 independent weight prefetch hides L2 latency.
// write_kernel: grid (2,256), 512 threads — at store-drain floor, unchanged.

#define NB 256
#define NN 20
#define DD 256
#define STRD 260        // smem row stride for [20][256] tiles

typedef unsigned long long ull;

__device__ float g_scratch[NB * 1200];   // per batch: P[400] | Q[400] | Mn[400]

#define FMA2(acc, x, y) \
    asm("fma.rn.f32x2 %0, %1, %2, %0;" : "+l"(acc) : "l"(x), "l"(y))

__device__ __forceinline__ float2 up64(ull v) {
    float2 r;
    asm("mov.b64 {%0,%1}, %2;" : "=f"(r.x), "=f"(r.y) : "l"(v));
    return r;
}
__device__ __forceinline__ ull dup(float w) {
    ull r;
    asm("mov.b64 %0, {%1,%1};" : "=l"(r) : "f"(w));
    return r;
}

// smem (floats): sA[5120] | sT1[5200] | sT2[5200] | sF[5200]
#define OFF_A  0
#define OFF_T1 5120
#define OFF_T2 10320
#define OFF_F  15520
#define SMEM_FLOATS 20720
#define SMEM_BYTES  (SMEM_FLOATS * 4)

// ---------------------------------------------------------------- compute ---
__global__ void __launch_bounds__(512, 2)
compute_kernel(const float* __restrict__ F1, const float* __restrict__ F2,
               const float* __restrict__ U1, const float* __restrict__ U2,
               const float* __restrict__ L1, const float* __restrict__ L2)
{
    extern __shared__ float sm[];
    float* sA  = sm + OFF_A;    // F1^T [d][20]
    float* sT1 = sm + OFF_T1;   // T1 [i][STRD] ; later U1 [i][STRD]
    float* sT2 = sm + OFF_T2;   // T2 [i][STRD] ; later U2 [k][STRD]
    float* sF  = sm + OFF_F;    // F2 [k][STRD]

    const int b = blockIdx.x;
    const int t = threadIdx.x;  // 0..511

    // 1. F1 transposed: sA[d*20+i] = F1[b,i,d]; F2 row-major into sF.
    {
        const float* f1 = F1 + (size_t)b * NN * DD;
        #pragma unroll
        for (int idx = t; idx < NN * DD; idx += 512) {
            int i = idx >> 8, d = idx & 255;
            sA[d * NN + i] = f1[idx];
        }
        const float4* f2v = reinterpret_cast<const float4*>(F2 + (size_t)b * NN * DD);
        #pragma unroll
        for (int i4 = t; i4 < NN * DD / 4; i4 += 512) {
            int k = i4 >> 6, d4 = i4 & 63;
            *reinterpret_cast<float4*>(sF + k * STRD + d4 * 4) = f2v[i4];
        }
    }
    __syncthreads();

    // 2. T[i,e] = sum_d F1[i,d]*relu(L[d,e]); one column per thread.
    {
        const int isQ = t >> 8;           // 0: L1/T1, 1: L2/T2
        const int e   = t & 255;
        const float* lp = (isQ ? L2 : L1) + e;
        float* sT = (isQ ? sT2 : sT1) + e;

        ull a[10];
        #pragma unroll
        for (int j = 0; j < 10; j++) a[j] = 0ull;

        float w[8];
        #pragma unroll
        for (int j = 0; j < 8; j++) w[j] = lp[j * DD];

        #pragma unroll 1
        for (int c = 0; c < DD; c += 8) {
            float wn[8];
            if (c + 8 < DD) {
                #pragma unroll
                for (int j = 0; j < 8; j++) wn[j] = lp[(c + 8 + j) * DD];
            }
            #pragma unroll
            for (int j = 0; j < 8; j++) {
                ull ww = dup(fmaxf(w[j], 0.f));
                const ulonglong2* row =
                    reinterpret_cast<const ulonglong2*>(sA + (c + j) * NN);
                #pragma unroll
                for (int v = 0; v < 5; v++) {
                    ulonglong2 fp = row[v];
                    FMA2(a[2 * v],     fp.x, ww);
                    FMA2(a[2 * v + 1], fp.y, ww);
                }
            }
            #pragma unroll
            for (int j = 0; j < 8; j++) w[j] = wn[j];
        }
        // store T row-major: sT[i*STRD + e]
        #pragma unroll
        for (int v = 0; v < 10; v++) {
            float2 f = up64(a[v]);
            sT[(2 * v) * STRD]     = f.x;
            sT[(2 * v + 1) * STRD] = f.y;
        }
    }
    __syncthreads();

    // 4. P[i,k] (idx<400) and Q[i,k] (idx>=400): 800 dots over 512 threads.
    {
        float* dst = g_scratch + b * 1200;
        #pragma unroll 1
        for (int idx = t; idx < 800; idx += 512) {
            int m = (idx >= 400) ? idx - 400 : idx;
            const float* Tbase = (idx >= 400) ? sT2 : sT1;
            int i = m / NN, k = m - i * NN;
            const ulonglong2* Ti = reinterpret_cast<const ulonglong2*>(Tbase + i * STRD);
            const ulonglong2* Fk = reinterpret_cast<const ulonglong2*>(sF + k * STRD);
            ull a0 = 0, a1 = 0, a2 = 0, a3 = 0;
            #pragma unroll
            for (int v = 0; v < DD / 4; v += 2) {
                ulonglong2 tv0 = Ti[v], tv1 = Ti[v + 1];
                ulonglong2 fv0 = Fk[v], fv1 = Fk[v + 1];
                FMA2(a0, tv0.x, fv0.x);
                FMA2(a1, tv0.y, fv0.y);
                FMA2(a2, tv1.x, fv1.x);
                FMA2(a3, tv1.y, fv1.y);
            }
            float2 s0 = up64(a0), s1 = up64(a1), s2 = up64(a2), s3 = up64(a3);
            dst[idx] = ((s0.x + s0.y) + (s1.x + s1.y)) +
                       ((s2.x + s2.y) + (s3.x + s3.y));
        }
    }
    __syncthreads();

    // 5. U1 -> sT1, U2 -> sT2, row-major
    {
        const float4* u1v = reinterpret_cast<const float4*>(U1 + (size_t)b * NN * DD);
        const float4* u2v = reinterpret_cast<const float4*>(U2 + (size_t)b * NN * DD);
        #pragma unroll
        for (int i4 = t; i4 < NN * DD / 4; i4 += 512) {
            int k = i4 >> 6, d4 = i4 & 63;
            *reinterpret_cast<float4*>(sT1 + k * STRD + d4 * 4) = u1v[i4];
            *reinterpret_cast<float4*>(sT2 + k * STRD + d4 * 4) = u2v[i4];
        }
    }
    __syncthreads();

    // 6. Mn[i,k] = U1[i].U2[k]
    if (t < 400) {
        int i = t / NN, k = t - i * NN;
        const ulonglong2* Ui = reinterpret_cast<const ulonglong2*>(sT1 + i * STRD);
        const ulonglong2* Uk = reinterpret_cast<const ulonglong2*>(sT2 + k * STRD);
        ull m0 = 0, m1 = 0, m2 = 0, m3 = 0;
        #pragma unroll
        for (int v = 0; v < DD / 4; v += 2) {
            ulonglong2 uv0 = Ui[v], uv1 = Ui[v + 1];
            ulonglong2 kv0 = Uk[v], kv1 = Uk[v + 1];
            FMA2(m0, uv0.x, kv0.x);
            FMA2(m1, uv0.y, kv0.y);
            FMA2(m2, uv1.x, kv1.x);
            FMA2(m3, uv1.y, kv1.y);
        }
        float2 s0 = up64(m0), s1 = up64(m1), s2 = up64(m2), s3 = up64(m3);
        g_scratch[b * 1200 + 800 + t] =
            ((s0.x + s0.y) + (s1.x + s1.y)) + ((s2.x + s2.y) + (s3.x + s3.y));
    }
}

// ------------------------------------------------------------------ write ---
__global__ void __launch_bounds__(512)
write_kernel(float* __restrict__ out)
{
    __shared__ __align__(16) float sPT[NN * 24];   // P^T: [q][y]
    __shared__ __align__(16) float sQT[NN * 24];   // Q^T: [p][y]
    __shared__ float sPd[NN * 21];                 // P: [x][p]
    __shared__ float sQd[NN * 21];                 // Q: [x][q]
    __shared__ float sMnD[NN * 21];                // Mn: [x][p]

    const int h = blockIdx.x;       // p-half: p in [h*10, h*10+10)
    const int b = blockIdx.y;
    const int t = threadIdx.x;

    const float* s = g_scratch + (size_t)b * 1200;

    if (t < 400) {
        int i = t / NN, k = t - i * NN;
        float pv = s[t], qv = s[400 + t], mv = s[800 + t];
        sPd[i * 21 + k] = pv;
        sPT[k * 24 + i] = pv;
        sQd[i * 21 + k] = qv;
        sQT[k * 24 + i] = qv;
        sMnD[i * 21 + k] = mv;
    }
    __syncthreads();

    if (t < 500) {
        const int x0 = t / 100;
        const int cm = t - x0 * 100;          // float4 index within row
        const int q  = cm / 5;
        const int y0 = (cm - q * 5) * 4;

        const float4 pt = *reinterpret_cast<const float4*>(sPT + q * 24 + y0);
        int   xs[4];
        float c2[4];
        int   dxv[4];
        #pragma unroll
        for (int j = 0; j < 4; j++) {
            xs[j]  = x0 + 5 * j;
            c2[j]  = sQd[xs[j] * 21 + q];
            dxv[j] = xs[j] - y0;
        }

        float4* ob = reinterpret_cast<float4*>(out) + (size_t)b * 40000 + cm;

        #pragma unroll 2
        for (int pp = 0; pp < 10; pp++) {
            const int p = h * 10 + pp;
            const float4 qc = *reinterpret_cast<const float4*>(sQT + p * 24 + y0);
            const float bx = pt.x + qc.x, by = pt.y + qc.y;
            const float bz = pt.z + qc.z, bw = pt.w + qc.w;
            float4* obp = ob + p * 2000;

            if (q != p) {
                #pragma unroll
                for (int j = 0; j < 4; j++) {
                    const int x = xs[j];
                    const float c1 = sPd[x * 21 + p] + c2[j];
                    float4 v = make_float4(c1 + bx, c1 + by, c1 + bz, c1 + bw);
                    const int dx = dxv[j];
                    if (dx == 0) v.x = 0.f;
                    else if (dx == 1) v.y = 0.f;
                    else if (dx == 2) v.z = 0.f;
                    else if (dx == 3) v.w = 0.f;
                    __stcs(&obp[x * 100], v);
                }
            } else {
                #pragma unroll
                for (int j = 0; j < 4; j++) {
                    const int x = xs[j];
                    float4 v = make_float4(0.f, 0.f, 0.f, 0.f);
                    const float mn = sMnD[x * 21 + p];
                    const int dx = dxv[j];
                    if (dx == 0) v.x = mn;
                    else if (dx == 1) v.y = mn;
                    else if (dx == 2) v.z = mn;
                    else if (dx == 3) v.w = mn;
                    __stcs(&obp[x * 100], v);
                }
            }
        }
    }
}

// ----------------------------------------------------------------- launch ---
extern "C" void kernel_launch(void* const* d_in, const int* in_sizes, int n_in,
                              void* d_out, int out_size)
{
    // Inputs: F1,F2,U1,U2,G1,G2,H1,H2,mask,lambda1,lambda2 — pick by size.
    const float* Fs[4] = {nullptr, nullptr, nullptr, nullptr};
    const float* Ls[2] = {nullptr, nullptr};
    int nf = 0, nl = 0;
    for (int i = 0; i < n_in; i++) {
        if (in_sizes[i] == NB * NN * DD) {
            if (nf < 4) Fs[nf++] = (const float*)d_in[i];
        } else if (in_sizes[i] == DD * DD) {
            if (nl < 2) Ls[nl++] = (const float*)d_in[i];
        }
    }

    cudaFuncSetAttribute(compute_kernel,
                         cudaFuncAttributeMaxDynamicSharedMemorySize, SMEM_BYTES);

    compute_kernel<<<NB, 512, SMEM_BYTES>>>(Fs[0], Fs[1], Fs[2], Fs[3],
                                            Ls[0], Ls[1]);
    write_kernel<<<dim3(2, NB), 512>>>((float*)d_out);
    (void)out_size;
}

// round 8
// speedup vs baseline: 1.2614x; 1.2614x over previous
#include <cuda_runtime.h>
#include <cstdint>

// out[b, p*20+x, q*20+y] = (x!=y && p!=q) ? P[x,p]+Q[x,q]+Q[y,p]+P[y,q] : 0
//                          + (p==q && x==y) ? Mn[x,p] : 0
// P = F1 @ relu(L1) @ F2^T, Q = F1 @ relu(L2) @ F2^T, Mn = U1 @ U2^T (per batch)
//
// compute_kernel: grid (2 i-halves, 256 batches), 128 threads, 4 CTAs/SM,
//   single wave. Thread owns 4 columns {L1,L2}x{2t,2t+1}: one A-row broadcast
//   (10 floats, 40B/lane) feeds 20 FFMA2 -> crossbar no longer binding.
// write_kernel: at DRAM store-drain floor (~28us), unchanged.

#define NB 256
#define NN 20
#define DD 256
#define HI 10           // i-rows per block
#define STRD 260        // smem row stride

typedef unsigned long long ull;

__device__ float g_scratch[NB * 1200];   // per batch: P[400] | Q[400] | Mn[400]

#define FMA2(acc, x, y) \
    asm("fma.rn.f32x2 %0, %1, %2, %0;" : "+l"(acc) : "l"(x), "l"(y))

__device__ __forceinline__ float2 up64(ull v) {
    float2 r;
    asm("mov.b64 {%0,%1}, %2;" : "=f"(r.x), "=f"(r.y) : "l"(v));
    return r;
}
__device__ __forceinline__ ull dup(float w) {
    ull r;
    asm("mov.b64 %0, {%1,%1};" : "=l"(r) : "f"(w));
    return r;
}

// smem (floats): sA[2600] | sT1[2600] | sT2[2600] | sF[5200]
//   sA: phase2 F1^T half [d][10]; phase6 U1 half [il][260]
//   sF: phase3 F2 full [k][260]; phase6 U2 full [k][260]
#define OFF_A  0
#define OFF_T1 2600
#define OFF_T2 5200
#define OFF_F  7800
#define SMEM_FLOATS 13000
#define SMEM_BYTES  (SMEM_FLOATS * 4)

// ---------------------------------------------------------------- compute ---
__global__ void __launch_bounds__(128, 4)
compute_kernel(const float* __restrict__ F1, const float* __restrict__ F2,
               const float* __restrict__ U1, const float* __restrict__ U2,
               const float* __restrict__ L1, const float* __restrict__ L2)
{
    extern __shared__ float sm[];
    float* sA  = sm + OFF_A;
    float* sT1 = sm + OFF_T1;   // T1 half [il][260]
    float* sT2 = sm + OFF_T2;   // T2 half [il][260]
    float* sF  = sm + OFF_F;    // F2 [k][260]

    const int hi = blockIdx.x;  // i-half: rows [hi*10, hi*10+10)
    const int b  = blockIdx.y;
    const int t  = threadIdx.x; // 0..127

    // 1. F1 half transposed: sA[d*10+il] = F1[b, hi*10+il, d]; F2 full -> sF
    {
        const float* f1 = F1 + ((size_t)b * NN + hi * HI) * DD;
        #pragma unroll
        for (int idx = t; idx < HI * DD; idx += 128) {
            int il = idx >> 8, d = idx & 255;
            sA[d * HI + il] = f1[il * DD + d];
        }
        const float4* f2v = reinterpret_cast<const float4*>(F2 + (size_t)b * NN * DD);
        #pragma unroll
        for (int i4 = t; i4 < NN * DD / 4; i4 += 128) {
            int k = i4 >> 6, d4 = i4 & 63;
            *reinterpret_cast<float4*>(sF + k * STRD + d4 * 4) = f2v[i4];
        }
    }
    __syncthreads();

    // 2. T1/T2 rows i-half, cols {2t, 2t+1}. Weights as float2 LDG.64,
    //    depth-8 prefetch. Per d: 5 LDS.64 A-broadcast -> 20 FFMA2.
    {
        const float2* l1p = reinterpret_cast<const float2*>(L1) + t;  // row d: [d*128]
        const float2* l2p = reinterpret_cast<const float2*>(L2) + t;

        ull a[2][2][5];   // [matrix][col-in-pair][i-pair]
        #pragma unroll
        for (int m = 0; m < 2; m++)
            #pragma unroll
            for (int c = 0; c < 2; c++)
                #pragma unroll
                for (int ip = 0; ip < 5; ip++) a[m][c][ip] = 0ull;

        float2 w1[8], w2[8];
        #pragma unroll
        for (int j = 0; j < 8; j++) { w1[j] = l1p[j * 128]; w2[j] = l2p[j * 128]; }

        #pragma unroll 1
        for (int cc = 0; cc < DD; cc += 8) {
            float2 n1[8], n2[8];
            if (cc + 8 < DD) {
                #pragma unroll
                for (int j = 0; j < 8; j++) {
                    n1[j] = l1p[(cc + 8 + j) * 128];
                    n2[j] = l2p[(cc + 8 + j) * 128];
                }
            }
            #pragma unroll
            for (int j = 0; j < 8; j++) {
                const int d = cc + j;
                ull w1x = dup(fmaxf(w1[j].x, 0.f));
                ull w1y = dup(fmaxf(w1[j].y, 0.f));
                ull w2x = dup(fmaxf(w2[j].x, 0.f));
                ull w2y = dup(fmaxf(w2[j].y, 0.f));
                const ull* row = reinterpret_cast<const ull*>(sA + d * HI);
                #pragma unroll
                for (int ip = 0; ip < 5; ip++) {
                    ull ap = row[ip];            // (F1[2ip,d], F1[2ip+1,d])
                    FMA2(a[0][0][ip], ap, w1x);
                    FMA2(a[0][1][ip], ap, w1y);
                    FMA2(a[1][0][ip], ap, w2x);
                    FMA2(a[1][1][ip], ap, w2y);
                }
            }
            #pragma unroll
            for (int j = 0; j < 8; j++) { w1[j] = n1[j]; w2[j] = n2[j]; }
        }

        // store T: sT[il][e], e = 2t + c
        #pragma unroll
        for (int ip = 0; ip < 5; ip++) {
            #pragma unroll
            for (int c = 0; c < 2; c++) {
                float2 f;
                f = up64(a[0][c][ip]);
                sT1[(2 * ip)     * STRD + 2 * t + c] = f.x;
                sT1[(2 * ip + 1) * STRD + 2 * t + c] = f.y;
                f = up64(a[1][c][ip]);
                sT2[(2 * ip)     * STRD + 2 * t + c] = f.x;
                sT2[(2 * ip + 1) * STRD + 2 * t + c] = f.y;
            }
        }
    }
    __syncthreads();

    // 4. P[i,k], Q[i,k] for i in this half (200 cells), shared F2-row read.
    {
        float* dst = g_scratch + b * 1200;
        #pragma unroll 1
        for (int idx = t; idx < HI * NN; idx += 128) {
            int il = idx / NN, k = idx - il * NN;
            const ulonglong2* Ti1 = reinterpret_cast<const ulonglong2*>(sT1 + il * STRD);
            const ulonglong2* Ti2 = reinterpret_cast<const ulonglong2*>(sT2 + il * STRD);
            const ulonglong2* Fk  = reinterpret_cast<const ulonglong2*>(sF  + k * STRD);
            ull p0 = 0, p1 = 0, q0 = 0, q1 = 0;
            #pragma unroll
            for (int v = 0; v < DD / 4; v++) {
                ulonglong2 fv = Fk[v];
                ulonglong2 t1 = Ti1[v];
                ulonglong2 t2 = Ti2[v];
                FMA2(p0, t1.x, fv.x);
                FMA2(p1, t1.y, fv.y);
                FMA2(q0, t2.x, fv.x);
                FMA2(q1, t2.y, fv.y);
            }
            float2 s0 = up64(p0), s1 = up64(p1);
            dst[(hi * HI + il) * NN + k] = (s0.x + s0.y) + (s1.x + s1.y);
            float2 s2 = up64(q0), s3 = up64(q1);
            dst[400 + (hi * HI + il) * NN + k] = (s2.x + s2.y) + (s3.x + s3.y);
        }
    }
    __syncthreads();

    // 5. U1 half -> sA [il][260]; U2 full -> sF [k][260]
    {
        const float4* u1v = reinterpret_cast<const float4*>(
            U1 + ((size_t)b * NN + hi * HI) * DD);
        const float4* u2v = reinterpret_cast<const float4*>(U2 + (size_t)b * NN * DD);
        #pragma unroll
        for (int i4 = t; i4 < HI * DD / 4; i4 += 128) {
            int il = i4 >> 6, d4 = i4 & 63;
            *reinterpret_cast<float4*>(sA + il * STRD + d4 * 4) = u1v[i4];
        }
        #pragma unroll
        for (int i4 = t; i4 < NN * DD / 4; i4 += 128) {
            int k = i4 >> 6, d4 = i4 & 63;
            *reinterpret_cast<float4*>(sF + k * STRD + d4 * 4) = u2v[i4];
        }
    }
    __syncthreads();

    // 6. Mn[i,k] = U1[i].U2[k], i in this half
    {
        float* dstM = g_scratch + b * 1200 + 800;
        #pragma unroll 1
        for (int idx = t; idx < HI * NN; idx += 128) {
            int il = idx / NN, k = idx - il * NN;
            const ulonglong2* Ui = reinterpret_cast<const ulonglong2*>(sA + il * STRD);
            const ulonglong2* Uk = reinterpret_cast<const ulonglong2*>(sF + k * STRD);
            ull m0 = 0, m1 = 0;
            #pragma unroll
            for (int v = 0; v < DD / 4; v++) {
                ulonglong2 uv = Ui[v];
                ulonglong2 kv = Uk[v];
                FMA2(m0, uv.x, kv.x);
                FMA2(m1, uv.y, kv.y);
            }
            float2 s0 = up64(m0), s1 = up64(m1);
            dstM[(hi * HI + il) * NN + k] = (s0.x + s0.y) + (s1.x + s1.y);
        }
    }
}

// ------------------------------------------------------------------ write ---
__global__ void __launch_bounds__(512)
write_kernel(float* __restrict__ out)
{
    __shared__ __align__(16) float sPT[NN * 24];   // P^T: [q][y]
    __shared__ __align__(16) float sQT[NN * 24];   // Q^T: [p][y]
    __shared__ float sPd[NN * 21];                 // P: [x][p]
    __shared__ float sQd[NN * 21];                 // Q: [x][q]
    __shared__ float sMnD[NN * 21];                // Mn: [x][p]

    const int h = blockIdx.x;       // p-half
    const int b = blockIdx.y;
    const int t = threadIdx.x;

    const float* s = g_scratch + (size_t)b * 1200;

    if (t < 400) {
        int i = t / NN, k = t - i * NN;
        float pv = s[t], qv = s[400 + t], mv = s[800 + t];
        sPd[i * 21 + k] = pv;
        sPT[k * 24 + i] = pv;
        sQd[i * 21 + k] = qv;
        sQT[k * 24 + i] = qv;
        sMnD[i * 21 + k] = mv;
    }
    __syncthreads();

    if (t < 500) {
        const int x0 = t / 100;
        const int cm = t - x0 * 100;
        const int q  = cm / 5;
        const int y0 = (cm - q * 5) * 4;

        const float4 pt = *reinterpret_cast<const float4*>(sPT + q * 24 + y0);
        int   xs[4];
        float c2[4];
        int   dxv[4];
        #pragma unroll
        for (int j = 0; j < 4; j++) {
            xs[j]  = x0 + 5 * j;
            c2[j]  = sQd[xs[j] * 21 + q];
            dxv[j] = xs[j] - y0;
        }

        float4* ob = reinterpret_cast<float4*>(out) + (size_t)b * 40000 + cm;

        #pragma unroll 2
        for (int pp = 0; pp < 10; pp++) {
            const int p = h * 10 + pp;
            const float4 qc = *reinterpret_cast<const float4*>(sQT + p * 24 + y0);
            const float bx = pt.x + qc.x, by = pt.y + qc.y;
            const float bz = pt.z + qc.z, bw = pt.w + qc.w;
            float4* obp = ob + p * 2000;

            if (q != p) {
                #pragma unroll
                for (int j = 0; j < 4; j++) {
                    const int x = xs[j];
                    const float c1 = sPd[x * 21 + p] + c2[j];
                    float4 v = make_float4(c1 + bx, c1 + by, c1 + bz, c1 + bw);
                    const int dx = dxv[j];
                    if (dx == 0) v.x = 0.f;
                    else if (dx == 1) v.y = 0.f;
                    else if (dx == 2) v.z = 0.f;
                    else if (dx == 3) v.w = 0.f;
                    __stcs(&obp[x * 100], v);
                }
            } else {
                #pragma unroll
                for (int j = 0; j < 4; j++) {
                    const int x = xs[j];
                    float4 v = make_float4(0.f, 0.f, 0.f, 0.f);
                    const float mn = sMnD[x * 21 + p];
                    const int dx = dxv[j];
                    if (dx == 0) v.x = mn;
                    else if (dx == 1) v.y = mn;
                    else if (dx == 2) v.z = mn;
                    else if (dx == 3) v.w = mn;
                    __stcs(&obp[x * 100], v);
                }
            }
        }
    }
}

// ----------------------------------------------------------------- launch ---
extern "C" void kernel_launch(void* const* d_in, const int* in_sizes, int n_in,
                              void* d_out, int out_size)
{
    // Inputs: F1,F2,U1,U2,G1,G2,H1,H2,mask,lambda1,lambda2 — pick by size.
    const float* Fs[4] = {nullptr, nullptr, nullptr, nullptr};
    const float* Ls[2] = {nullptr, nullptr};
    int nf = 0, nl = 0;
    for (int i = 0; i < n_in; i++) {
        if (in_sizes[i] == NB * NN * DD) {
            if (nf < 4) Fs[nf++] = (const float*)d_in[i];
        } else if (in_sizes[i] == DD * DD) {
            if (nl < 2) Ls[nl++] = (const float*)d_in[i];
        }
    }

    cudaFuncSetAttribute(compute_kernel,
                         cudaFuncAttributeMaxDynamicSharedMemorySize, SMEM_BYTES);

    compute_kernel<<<dim3(2, NB), 128, SMEM_BYTES>>>(Fs[0], Fs[1], Fs[2], Fs[3],
                                                     Ls[0], Ls[1]);
    write_kernel<<<dim3(2, NB), 512>>>((float*)d_out);
    (void)out_size;
}

// round 10
// speedup vs baseline: 1.3272x; 1.0521x over previous
#include <cuda_runtime.h>
#include <cuda_bf16.h>
#include <cstdint>

// out[b, p*20+x, q*20+y] = (x!=y && p!=q) ? P[x,p]+Q[x,q]+Q[y,p]+P[y,q] : 0
//                          + (p==q && x==y) ? Mn[x,p] : 0
// P = F1 @ relu(L1) @ F2^T, Q = F1 @ relu(L2) @ F2^T, Mn = U1 @ U2^T.
//
// Stage 1: T[5120,512] = F1all[5120,256] @ [relu(L1)|relu(L2)] on tensor cores
// via baseline-PTX mma.sync m16n8k16 bf16 (compute_103-safe; tcgen05 is
// blocked by the harness's non-'a' PTX target). bf16 hi/lo split, 3 passes.
// Fragments are PRE-PACKED per lane by prep_kernel so the GEMM inner loop is
// LDG.128 + HMMA only. Then pq_kernel (small) + drain-bound write_kernel.

#define NB 256
#define NN 20
#define DD 256
#define MROWS (NB * NN)        // 5120
#define NCOLS (2 * DD)         // 512
#define MB16  (MROWS / 16)     // 320 m16 blocks
#define KB16  (DD / 16)        // 16 k16 blocks
#define NB16  (NCOLS / 16)     // 32 n16 (pair of n8) blocks

typedef unsigned long long ull;

// ---- device scratch ----
__device__ uint4 g_Ah[MB16 * KB16 * 32];   // per-lane A fragments (hi)
__device__ uint4 g_Al[MB16 * KB16 * 32];   // (lo)
__device__ uint4 g_Bh[NB16 * KB16 * 32];   // per-lane B fragment pairs (hi)
__device__ uint4 g_Bl[NB16 * KB16 * 32];   // (lo)
__device__ float g_T[MROWS * NCOLS];       // 10.5 MB
__device__ float g_scratch[NB * 1200];     // P[400] | Q[400] | Mn[400]

// ---- helpers ----
__device__ __forceinline__ uint32_t pk2(float x, float y) {
    __nv_bfloat162 v = __floats2bfloat162_rn(x, y);   // .x in low half
    return *reinterpret_cast<uint32_t*>(&v);
}
__device__ __forceinline__ float bfhi(float x) {
    return __bfloat162float(__float2bfloat16_rn(x));
}

#define MMA_BF16(c, a, b0, b1)                                              \
    asm volatile("mma.sync.aligned.m16n8k16.row.col.f32.bf16.bf16.f32 "     \
        "{%0,%1,%2,%3}, {%4,%5,%6,%7}, {%8,%9}, {%0,%1,%2,%3};"             \
        : "+f"((c)[0]), "+f"((c)[1]), "+f"((c)[2]), "+f"((c)[3])            \
        : "r"((a).x), "r"((a).y), "r"((a).z), "r"((a).w), "r"(b0), "r"(b1))

// ------------------------------------------------------------------- prep ---
// tid < 163840: A fragments. thread = (mb, kb, lane).
//   a0=A[g][2t,2t+1], a1=A[g+8][..], a2=A[g][8+2t,..], a3=A[g+8][8+2t,..]
// tid >= 163840: B fragment pairs. thread = (nb2, kb, lane), n-tile n0=nb2*16.
//   x=b0(n=g): B[2t..2t+1][n],  y=b1(n=g): B[8+2t..][n],  z,w: same at n+8.
//   B[k][n] = relu(L[k][n]) with column n<256 -> L1, else L2.
__global__ void __launch_bounds__(256)
prep_kernel(const float* __restrict__ F1, const float* __restrict__ L1,
            const float* __restrict__ L2)
{
    const int tid = blockIdx.x * 256 + threadIdx.x;
    if (tid < MB16 * KB16 * 32) {
        const int lane = tid & 31;
        const int kb   = (tid >> 5) & 15;
        const int mb   = tid >> 9;
        const int g = lane >> 2, t = lane & 3;
        const float* r0 = F1 + (size_t)(mb * 16 + g) * DD + kb * 16;
        const float* r1 = r0 + 8 * DD;
        float2 f00 = *reinterpret_cast<const float2*>(r0 + 2 * t);
        float2 f01 = *reinterpret_cast<const float2*>(r0 + 8 + 2 * t);
        float2 f10 = *reinterpret_cast<const float2*>(r1 + 2 * t);
        float2 f11 = *reinterpret_cast<const float2*>(r1 + 8 + 2 * t);
        uint4 h, l;
        h.x = pk2(f00.x, f00.y);
        h.y = pk2(f10.x, f10.y);
        h.z = pk2(f01.x, f01.y);
        h.w = pk2(f11.x, f11.y);
        l.x = pk2(f00.x - bfhi(f00.x), f00.y - bfhi(f00.y));
        l.y = pk2(f10.x - bfhi(f10.x), f10.y - bfhi(f10.y));
        l.z = pk2(f01.x - bfhi(f01.x), f01.y - bfhi(f01.y));
        l.w = pk2(f11.x - bfhi(f11.x), f11.y - bfhi(f11.y));
        g_Ah[tid] = h;
        g_Al[tid] = l;
    } else {
        const int s    = tid - MB16 * KB16 * 32;
        const int lane = s & 31;
        const int kb   = (s >> 5) & 15;
        const int nb2  = s >> 9;          // 0..31
        const int g = lane >> 2, t = lane & 3;
        const int n0 = nb2 * 16 + g;      // whole nb2 lies in one matrix
        const float* Ls = (n0 < DD) ? L1 : L2;
        const int nc  = (n0 < DD) ? n0 : n0 - DD;
        const int k0  = kb * 16;
        float w0a = fmaxf(Ls[(k0 + 2 * t)     * DD + nc], 0.f);
        float w0b = fmaxf(Ls[(k0 + 2 * t + 1) * DD + nc], 0.f);
        float w1a = fmaxf(Ls[(k0 + 8 + 2 * t) * DD + nc], 0.f);
        float w1b = fmaxf(Ls[(k0 + 9 + 2 * t) * DD + nc], 0.f);
        float w2a = fmaxf(Ls[(k0 + 2 * t)     * DD + nc + 8], 0.f);
        float w2b = fmaxf(Ls[(k0 + 2 * t + 1) * DD + nc + 8], 0.f);
        float w3a = fmaxf(Ls[(k0 + 8 + 2 * t) * DD + nc + 8], 0.f);
        float w3b = fmaxf(Ls[(k0 + 9 + 2 * t) * DD + nc + 8], 0.f);
        uint4 h, l;
        h.x = pk2(w0a, w0b);
        h.y = pk2(w1a, w1b);
        h.z = pk2(w2a, w2b);
        h.w = pk2(w3a, w3b);
        l.x = pk2(w0a - bfhi(w0a), w0b - bfhi(w0b));
        l.y = pk2(w1a - bfhi(w1a), w1b - bfhi(w1b));
        l.z = pk2(w2a - bfhi(w2a), w2b - bfhi(w2b));
        l.w = pk2(w3a - bfhi(w3a), w3b - bfhi(w3b));
        g_Bh[s] = h;
        g_Bl[s] = l;
    }
}

// ------------------------------------------------------------------- gemm ---
// grid (8 n-blocks of 64, 40 m-blocks of 128), 256 threads = 8 warps.
// warp w: rows [blockIdx.y*128 + w*16, +16), all 64 cols (8 n8-tiles).
__global__ void __launch_bounds__(256)
gemm_kernel()
{
    const int w    = threadIdx.x >> 5;
    const int lane = threadIdx.x & 31;
    const int mb   = blockIdx.y * 8 + w;       // m16-block 0..319
    const int nb0  = blockIdx.x * 4;           // nb2 base (4 pairs = 64 cols)

    float c[8][4];
    #pragma unroll
    for (int nt = 0; nt < 8; nt++)
        #pragma unroll
        for (int v = 0; v < 4; v++) c[nt][v] = 0.f;

    #pragma unroll 1
    for (int kb = 0; kb < KB16; kb++) {
        const uint4 ah = g_Ah[(mb * KB16 + kb) * 32 + lane];
        const uint4 al = g_Al[(mb * KB16 + kb) * 32 + lane];
        #pragma unroll
        for (int j = 0; j < 4; j++) {
            const uint4 bh = g_Bh[((nb0 + j) * KB16 + kb) * 32 + lane];
            const uint4 bl = g_Bl[((nb0 + j) * KB16 + kb) * 32 + lane];
            MMA_BF16(c[2 * j],     ah, bh.x, bh.y);
            MMA_BF16(c[2 * j],     ah, bl.x, bl.y);
            MMA_BF16(c[2 * j],     al, bh.x, bh.y);
            MMA_BF16(c[2 * j + 1], ah, bh.z, bh.w);
            MMA_BF16(c[2 * j + 1], ah, bl.z, bl.w);
            MMA_BF16(c[2 * j + 1], al, bh.z, bh.w);
        }
    }

    // epilogue: c0,c1 -> D[g][2t,2t+1]; c2,c3 -> D[g+8][..]
    const int g = lane >> 2, t = lane & 3;
    float* base0 = g_T + (size_t)(mb * 16 + g) * NCOLS + blockIdx.x * 64 + 2 * t;
    float* base1 = base0 + 8 * NCOLS;
    #pragma unroll
    for (int nt = 0; nt < 8; nt++) {
        *reinterpret_cast<float2*>(base0 + nt * 8) = make_float2(c[nt][0], c[nt][1]);
        *reinterpret_cast<float2*>(base1 + nt * 8) = make_float2(c[nt][2], c[nt][3]);
    }
}

// --------------------------------------------------------------------- pq ---
#define STRD 260
#define FMA2(acc, x, y) \
    asm("fma.rn.f32x2 %0, %1, %2, %0;" : "+l"(acc) : "l"(x), "l"(y))
__device__ __forceinline__ float2 up64(ull v) {
    float2 r;
    asm("mov.b64 {%0,%1}, %2;" : "=f"(r.x), "=f"(r.y) : "l"(v));
    return r;
}

__global__ void __launch_bounds__(256)
pq_kernel(const float* __restrict__ F2, const float* __restrict__ U1,
          const float* __restrict__ U2)
{
    extern __shared__ float sm[];
    float* sT1 = sm;               // [20][260]
    float* sT2 = sm + NN * STRD;
    float* sF  = sm + 2 * NN * STRD;

    const int b = blockIdx.x;
    const int t = threadIdx.x;

    {
        const float4* Tv = reinterpret_cast<const float4*>(g_T + (size_t)b * NN * NCOLS);
        #pragma unroll
        for (int i4 = t; i4 < NN * 128; i4 += 256) {
            int i = i4 >> 7, c = i4 & 127;
            float4 v = Tv[i * 128 + c];
            if (c < 64) *reinterpret_cast<float4*>(sT1 + i * STRD + c * 4) = v;
            else        *reinterpret_cast<float4*>(sT2 + i * STRD + (c - 64) * 4) = v;
        }
        const float4* f2v = reinterpret_cast<const float4*>(F2 + (size_t)b * NN * DD);
        #pragma unroll
        for (int i4 = t; i4 < NN * 64; i4 += 256) {
            int k = i4 >> 6, d4 = i4 & 63;
            *reinterpret_cast<float4*>(sF + k * STRD + d4 * 4) = f2v[i4];
        }
    }
    __syncthreads();

    {
        float* dst = g_scratch + b * 1200;
        #pragma unroll 1
        for (int idx = t; idx < 800; idx += 256) {
            int m = (idx >= 400) ? idx - 400 : idx;
            const float* Tb = (idx >= 400) ? sT2 : sT1;
            int i = m / NN, k = m - i * NN;
            const ulonglong2* Ti = reinterpret_cast<const ulonglong2*>(Tb + i * STRD);
            const ulonglong2* Fk = reinterpret_cast<const ulonglong2*>(sF + k * STRD);
            ull a0 = 0, a1 = 0, a2 = 0, a3 = 0;
            #pragma unroll
            for (int v = 0; v < DD / 4; v += 2) {
                ulonglong2 t0 = Ti[v], t1 = Ti[v + 1];
                ulonglong2 f0 = Fk[v], f1 = Fk[v + 1];
                FMA2(a0, t0.x, f0.x);
                FMA2(a1, t0.y, f0.y);
                FMA2(a2, t1.x, f1.x);
                FMA2(a3, t1.y, f1.y);
            }
            float2 s0 = up64(a0), s1 = up64(a1), s2 = up64(a2), s3 = up64(a3);
            dst[idx] = ((s0.x + s0.y) + (s1.x + s1.y)) +
                       ((s2.x + s2.y) + (s3.x + s3.y));
        }
    }
    __syncthreads();

    {
        const float4* u1v = reinterpret_cast<const float4*>(U1 + (size_t)b * NN * DD);
        const float4* u2v = reinterpret_cast<const float4*>(U2 + (size_t)b * NN * DD);
        #pragma unroll
        for (int i4 = t; i4 < NN * 64; i4 += 256) {
            int k = i4 >> 6, d4 = i4 & 63;
            *reinterpret_cast<float4*>(sT1 + k * STRD + d4 * 4) = u1v[i4];
            *reinterpret_cast<float4*>(sT2 + k * STRD + d4 * 4) = u2v[i4];
        }
    }
    __syncthreads();

    {
        float* dstM = g_scratch + b * 1200 + 800;
        #pragma unroll 1
        for (int idx = t; idx < 400; idx += 256) {
            int i = idx / NN, k = idx - i * NN;
            const ulonglong2* Ui = reinterpret_cast<const ulonglong2*>(sT1 + i * STRD);
            const ulonglong2* Uk = reinterpret_cast<const ulonglong2*>(sT2 + k * STRD);
            ull m0 = 0, m1 = 0;
            #pragma unroll
            for (int v = 0; v < DD / 4; v++) {
                ulonglong2 uv = Ui[v];
                ulonglong2 kv = Uk[v];
                FMA2(m0, uv.x, kv.x);
                FMA2(m1, uv.y, kv.y);
            }
            float2 s0 = up64(m0), s1 = up64(m1);
            dstM[idx] = (s0.x + s0.y) + (s1.x + s1.y);
        }
    }
}

// ------------------------------------------------------------------ write ---
__global__ void __launch_bounds__(512)
write_kernel(float* __restrict__ out)
{
    __shared__ __align__(16) float sPT[NN * 24];
    __shared__ __align__(16) float sQT[NN * 24];
    __shared__ float sPd[NN * 21];
    __shared__ float sQd[NN * 21];
    __shared__ float sMnD[NN * 21];

    const int h = blockIdx.x;
    const int b = blockIdx.y;
    const int t = threadIdx.x;

    const float* s = g_scratch + (size_t)b * 1200;

    if (t < 400) {
        int i = t / NN, k = t - i * NN;
        float pv = s[t], qv = s[400 + t], mv = s[800 + t];
        sPd[i * 21 + k] = pv;
        sPT[k * 24 + i] = pv;
        sQd[i * 21 + k] = qv;
        sQT[k * 24 + i] = qv;
        sMnD[i * 21 + k] = mv;
    }
    __syncthreads();

    if (t < 500) {
        const int x0 = t / 100;
        const int cm = t - x0 * 100;
        const int q  = cm / 5;
        const int y0 = (cm - q * 5) * 4;

        const float4 pt = *reinterpret_cast<const float4*>(sPT + q * 24 + y0);
        int   xs[4];
        float c2[4];
        int   dxv[4];
        #pragma unroll
        for (int j = 0; j < 4; j++) {
            xs[j]  = x0 + 5 * j;
            c2[j]  = sQd[xs[j] * 21 + q];
            dxv[j] = xs[j] - y0;
        }

        float4* ob = reinterpret_cast<float4*>(out) + (size_t)b * 40000 + cm;

        #pragma unroll 2
        for (int pp = 0; pp < 10; pp++) {
            const int p = h * 10 + pp;
            const float4 qc = *reinterpret_cast<const float4*>(sQT + p * 24 + y0);
            const float bx = pt.x + qc.x, by = pt.y + qc.y;
            const float bz = pt.z + qc.z, bw = pt.w + qc.w;
            float4* obp = ob + p * 2000;

            if (q != p) {
                #pragma unroll
                for (int j = 0; j < 4; j++) {
                    const int x = xs[j];
                    const float c1 = sPd[x * 21 + p] + c2[j];
                    float4 v = make_float4(c1 + bx, c1 + by, c1 + bz, c1 + bw);
                    const int dx = dxv[j];
                    if (dx == 0) v.x = 0.f;
                    else if (dx == 1) v.y = 0.f;
                    else if (dx == 2) v.z = 0.f;
                    else if (dx == 3) v.w = 0.f;
                    __stcs(&obp[x * 100], v);
                }
            } else {
                #pragma unroll
                for (int j = 0; j < 4; j++) {
                    const int x = xs[j];
                    float4 v = make_float4(0.f, 0.f, 0.f, 0.f);
                    const float mn = sMnD[x * 21 + p];
                    const int dx = dxv[j];
                    if (dx == 0) v.x = mn;
                    else if (dx == 1) v.y = mn;
                    else if (dx == 2) v.z = mn;
                    else if (dx == 3) v.w = mn;
                    __stcs(&obp[x * 100], v);
                }
            }
        }
    }
}

// ----------------------------------------------------------------- launch ---
extern "C" void kernel_launch(void* const* d_in, const int* in_sizes, int n_in,
                              void* d_out, int out_size)
{
    // Inputs: F1,F2,U1,U2,G1,G2,H1,H2,mask,lambda1,lambda2 — pick by size.
    const float* Fs[4] = {nullptr, nullptr, nullptr, nullptr};
    const float* Ls[2] = {nullptr, nullptr};
    int nf = 0, nl = 0;
    for (int i = 0; i < n_in; i++) {
        if (in_sizes[i] == NB * NN * DD) {
            if (nf < 4) Fs[nf++] = (const float*)d_in[i];
        } else if (in_sizes[i] == DD * DD) {
            if (nl < 2) Ls[nl++] = (const float*)d_in[i];
        }
    }

    const int pq_smem = 3 * NN * STRD * (int)sizeof(float);
    cudaFuncSetAttribute(pq_kernel,
                         cudaFuncAttributeMaxDynamicSharedMemorySize, pq_smem);

    const int prep_threads = MB16 * KB16 * 32 + NB16 * KB16 * 32;  // 180224
    prep_kernel<<<prep_threads / 256, 256>>>(Fs[0], Ls[0], Ls[1]);
    gemm_kernel<<<dim3(8, 40), 256>>>();
    pq_kernel<<<NB, 256, pq_smem>>>(Fs[1], Fs[2], Fs[3]);
    write_kernel<<<dim3(2, NB), 512>>>((float*)d_out);
    (void)out_size;
}

// round 11
// speedup vs baseline: 1.3277x; 1.0004x over previous
#include <cuda_runtime.h>
#include <cuda_bf16.h>
#include <cstdint>

// out[b, p*20+x, q*20+y] = (x!=y && p!=q) ? P[x,p]+Q[x,q]+Q[y,p]+P[y,q] : 0
//                          + (p==q && x==y) ? Mn[x,p] : 0
// P = F1 @ relu(L1) @ F2^T, Q = F1 @ relu(L2) @ F2^T, Mn = U1 @ U2^T.
//
// Stage 1: T[5120,512] = F1all @ [relu(L1)|relu(L2)] via mma.sync m16n8k16
// bf16 hi/lo split (3 passes). R11: A-fragment register double-buffering +
// __ldcs streaming A + batched B loads to kill per-kb latency exposure.

#define NB 256
#define NN 20
#define DD 256
#define MROWS (NB * NN)        // 5120
#define NCOLS (2 * DD)         // 512
#define MB16  (MROWS / 16)     // 320
#define KB16  (DD / 16)        // 16
#define NB16  (NCOLS / 16)     // 32

typedef unsigned long long ull;

// ---- device scratch ----
__device__ uint4 g_Ah[MB16 * KB16 * 32];
__device__ uint4 g_Al[MB16 * KB16 * 32];
__device__ uint4 g_Bh[NB16 * KB16 * 32];
__device__ uint4 g_Bl[NB16 * KB16 * 32];
__device__ float g_T[MROWS * NCOLS];
__device__ float g_scratch[NB * 1200];     // P[400] | Q[400] | Mn[400]

// ---- helpers ----
__device__ __forceinline__ uint32_t pk2(float x, float y) {
    __nv_bfloat162 v = __floats2bfloat162_rn(x, y);
    return *reinterpret_cast<uint32_t*>(&v);
}
__device__ __forceinline__ float bfhi(float x) {
    return __bfloat162float(__float2bfloat16_rn(x));
}

#define MMA_BF16(c, a, b0, b1)                                              \
    asm volatile("mma.sync.aligned.m16n8k16.row.col.f32.bf16.bf16.f32 "     \
        "{%0,%1,%2,%3}, {%4,%5,%6,%7}, {%8,%9}, {%0,%1,%2,%3};"             \
        : "+f"((c)[0]), "+f"((c)[1]), "+f"((c)[2]), "+f"((c)[3])            \
        : "r"((a).x), "r"((a).y), "r"((a).z), "r"((a).w), "r"(b0), "r"(b1))

// ------------------------------------------------------------------- prep ---
__global__ void __launch_bounds__(256)
prep_kernel(const float* __restrict__ F1, const float* __restrict__ L1,
            const float* __restrict__ L2)
{
    const int tid = blockIdx.x * 256 + threadIdx.x;
    if (tid < MB16 * KB16 * 32) {
        const int lane = tid & 31;
        const int kb   = (tid >> 5) & 15;
        const int mb   = tid >> 9;
        const int g = lane >> 2, t = lane & 3;
        const float* r0 = F1 + (size_t)(mb * 16 + g) * DD + kb * 16;
        const float* r1 = r0 + 8 * DD;
        float2 f00 = *reinterpret_cast<const float2*>(r0 + 2 * t);
        float2 f01 = *reinterpret_cast<const float2*>(r0 + 8 + 2 * t);
        float2 f10 = *reinterpret_cast<const float2*>(r1 + 2 * t);
        float2 f11 = *reinterpret_cast<const float2*>(r1 + 8 + 2 * t);
        uint4 h, l;
        h.x = pk2(f00.x, f00.y);
        h.y = pk2(f10.x, f10.y);
        h.z = pk2(f01.x, f01.y);
        h.w = pk2(f11.x, f11.y);
        l.x = pk2(f00.x - bfhi(f00.x), f00.y - bfhi(f00.y));
        l.y = pk2(f10.x - bfhi(f10.x), f10.y - bfhi(f10.y));
        l.z = pk2(f01.x - bfhi(f01.x), f01.y - bfhi(f01.y));
        l.w = pk2(f11.x - bfhi(f11.x), f11.y - bfhi(f11.y));
        g_Ah[tid] = h;
        g_Al[tid] = l;
    } else {
        const int s    = tid - MB16 * KB16 * 32;
        const int lane = s & 31;
        const int kb   = (s >> 5) & 15;
        const int nb2  = s >> 9;
        const int g = lane >> 2, t = lane & 3;
        const int n0 = nb2 * 16 + g;
        const float* Ls = (n0 < DD) ? L1 : L2;
        const int nc  = (n0 < DD) ? n0 : n0 - DD;
        const int k0  = kb * 16;
        float w0a = fmaxf(Ls[(k0 + 2 * t)     * DD + nc], 0.f);
        float w0b = fmaxf(Ls[(k0 + 2 * t + 1) * DD + nc], 0.f);
        float w1a = fmaxf(Ls[(k0 + 8 + 2 * t) * DD + nc], 0.f);
        float w1b = fmaxf(Ls[(k0 + 9 + 2 * t) * DD + nc], 0.f);
        float w2a = fmaxf(Ls[(k0 + 2 * t)     * DD + nc + 8], 0.f);
        float w2b = fmaxf(Ls[(k0 + 2 * t + 1) * DD + nc + 8], 0.f);
        float w3a = fmaxf(Ls[(k0 + 8 + 2 * t) * DD + nc + 8], 0.f);
        float w3b = fmaxf(Ls[(k0 + 9 + 2 * t) * DD + nc + 8], 0.f);
        uint4 h, l;
        h.x = pk2(w0a, w0b);
        h.y = pk2(w1a, w1b);
        h.z = pk2(w2a, w2b);
        h.w = pk2(w3a, w3b);
        l.x = pk2(w0a - bfhi(w0a), w0b - bfhi(w0b));
        l.y = pk2(w1a - bfhi(w1a), w1b - bfhi(w1b));
        l.z = pk2(w2a - bfhi(w2a), w2b - bfhi(w2b));
        l.w = pk2(w3a - bfhi(w3a), w3b - bfhi(w3b));
        g_Bh[s] = h;
        g_Bl[s] = l;
    }
}

// ------------------------------------------------------------------- gemm ---
__global__ void __launch_bounds__(256)
gemm_kernel()
{
    const int w    = threadIdx.x >> 5;
    const int lane = threadIdx.x & 31;
    const int mb   = blockIdx.y * 8 + w;       // m16-block
    const int nb0  = blockIdx.x * 4;           // nb2 base

    float c[8][4];
    #pragma unroll
    for (int nt = 0; nt < 8; nt++)
        #pragma unroll
        for (int v = 0; v < 4; v++) c[nt][v] = 0.f;

    const uint4* Ahp = g_Ah + (size_t)mb * KB16 * 32 + lane;
    const uint4* Alp = g_Al + (size_t)mb * KB16 * 32 + lane;

    // A double-buffer: streamed (read-once) loads, evict-first so B stays in L1
    uint4 ah = __ldcs(Ahp);
    uint4 al = __ldcs(Alp);

    #pragma unroll 1
    for (int kb = 0; kb < KB16; kb++) {
        // batch all B loads for this kb (L1-hit for warps 1..7)
        uint4 bh[4], bl[4];
        #pragma unroll
        for (int j = 0; j < 4; j++) {
            bh[j] = g_Bh[((nb0 + j) * KB16 + kb) * 32 + lane];
            bl[j] = g_Bl[((nb0 + j) * KB16 + kb) * 32 + lane];
        }
        // prefetch next A
        uint4 ahn = ah, aln = al;
        if (kb + 1 < KB16) {
            ahn = __ldcs(Ahp + (kb + 1) * 32);
            aln = __ldcs(Alp + (kb + 1) * 32);
        }
        // 24 MMAs on current A
        #pragma unroll
        for (int j = 0; j < 4; j++) {
            MMA_BF16(c[2 * j],     ah, bh[j].x, bh[j].y);
            MMA_BF16(c[2 * j],     ah, bl[j].x, bl[j].y);
            MMA_BF16(c[2 * j],     al, bh[j].x, bh[j].y);
            MMA_BF16(c[2 * j + 1], ah, bh[j].z, bh[j].w);
            MMA_BF16(c[2 * j + 1], ah, bl[j].z, bl[j].w);
            MMA_BF16(c[2 * j + 1], al, bh[j].z, bh[j].w);
        }
        ah = ahn;
        al = aln;
    }

    const int g = lane >> 2, t = lane & 3;
    float* base0 = g_T + (size_t)(mb * 16 + g) * NCOLS + blockIdx.x * 64 + 2 * t;
    float* base1 = base0 + 8 * NCOLS;
    #pragma unroll
    for (int nt = 0; nt < 8; nt++) {
        *reinterpret_cast<float2*>(base0 + nt * 8) = make_float2(c[nt][0], c[nt][1]);
        *reinterpret_cast<float2*>(base1 + nt * 8) = make_float2(c[nt][2], c[nt][3]);
    }
}

// --------------------------------------------------------------------- pq ---
#define STRD 260
#define FMA2(acc, x, y) \
    asm("fma.rn.f32x2 %0, %1, %2, %0;" : "+l"(acc) : "l"(x), "l"(y))
__device__ __forceinline__ float2 up64(ull v) {
    float2 r;
    asm("mov.b64 {%0,%1}, %2;" : "=f"(r.x), "=f"(r.y) : "l"(v));
    return r;
}

__global__ void __launch_bounds__(256)
pq_kernel(const float* __restrict__ F2, const float* __restrict__ U1,
          const float* __restrict__ U2)
{
    extern __shared__ float sm[];
    float* sT1 = sm;
    float* sT2 = sm + NN * STRD;
    float* sF  = sm + 2 * NN * STRD;

    const int b = blockIdx.x;
    const int t = threadIdx.x;

    {
        const float4* Tv = reinterpret_cast<const float4*>(g_T + (size_t)b * NN * NCOLS);
        #pragma unroll
        for (int i4 = t; i4 < NN * 128; i4 += 256) {
            int i = i4 >> 7, c = i4 & 127;
            float4 v = Tv[i * 128 + c];
            if (c < 64) *reinterpret_cast<float4*>(sT1 + i * STRD + c * 4) = v;
            else        *reinterpret_cast<float4*>(sT2 + i * STRD + (c - 64) * 4) = v;
        }
        const float4* f2v = reinterpret_cast<const float4*>(F2 + (size_t)b * NN * DD);
        #pragma unroll
        for (int i4 = t; i4 < NN * 64; i4 += 256) {
            int k = i4 >> 6, d4 = i4 & 63;
            *reinterpret_cast<float4*>(sF + k * STRD + d4 * 4) = f2v[i4];
        }
    }
    __syncthreads();

    {
        float* dst = g_scratch + b * 1200;
        #pragma unroll 1
        for (int idx = t; idx < 800; idx += 256) {
            int m = (idx >= 400) ? idx - 400 : idx;
            const float* Tb = (idx >= 400) ? sT2 : sT1;
            int i = m / NN, k = m - i * NN;
            const ulonglong2* Ti = reinterpret_cast<const ulonglong2*>(Tb + i * STRD);
            const ulonglong2* Fk = reinterpret_cast<const ulonglong2*>(sF + k * STRD);
            ull a0 = 0, a1 = 0, a2 = 0, a3 = 0;
            #pragma unroll
            for (int v = 0; v < DD / 4; v += 2) {
                ulonglong2 t0 = Ti[v], t1 = Ti[v + 1];
                ulonglong2 f0 = Fk[v], f1 = Fk[v + 1];
                FMA2(a0, t0.x, f0.x);
                FMA2(a1, t0.y, f0.y);
                FMA2(a2, t1.x, f1.x);
                FMA2(a3, t1.y, f1.y);
            }
            float2 s0 = up64(a0), s1 = up64(a1), s2 = up64(a2), s3 = up64(a3);
            dst[idx] = ((s0.x + s0.y) + (s1.x + s1.y)) +
                       ((s2.x + s2.y) + (s3.x + s3.y));
        }
    }
    __syncthreads();

    {
        const float4* u1v = reinterpret_cast<const float4*>(U1 + (size_t)b * NN * DD);
        const float4* u2v = reinterpret_cast<const float4*>(U2 + (size_t)b * NN * DD);
        #pragma unroll
        for (int i4 = t; i4 < NN * 64; i4 += 256) {
            int k = i4 >> 6, d4 = i4 & 63;
            *reinterpret_cast<float4*>(sT1 + k * STRD + d4 * 4) = u1v[i4];
            *reinterpret_cast<float4*>(sT2 + k * STRD + d4 * 4) = u2v[i4];
        }
    }
    __syncthreads();

    {
        float* dstM = g_scratch + b * 1200 + 800;
        #pragma unroll 1
        for (int idx = t; idx < 400; idx += 256) {
            int i = idx / NN, k = idx - i * NN;
            const ulonglong2* Ui = reinterpret_cast<const ulonglong2*>(sT1 + i * STRD);
            const ulonglong2* Uk = reinterpret_cast<const ulonglong2*>(sT2 + k * STRD);
            ull m0 = 0, m1 = 0;
            #pragma unroll
            for (int v = 0; v < DD / 4; v++) {
                ulonglong2 uv = Ui[v];
                ulonglong2 kv = Uk[v];
                FMA2(m0, uv.x, kv.x);
                FMA2(m1, uv.y, kv.y);
            }
            float2 s0 = up64(m0), s1 = up64(m1);
            dstM[idx] = (s0.x + s0.y) + (s1.x + s1.y);
        }
    }
}

// ------------------------------------------------------------------ write ---
__global__ void __launch_bounds__(512)
write_kernel(float* __restrict__ out)
{
    __shared__ __align__(16) float sPT[NN * 24];
    __shared__ __align__(16) float sQT[NN * 24];
    __shared__ float sPd[NN * 21];
    __shared__ float sQd[NN * 21];
    __shared__ float sMnD[NN * 21];

    const int h = blockIdx.x;
    const int b = blockIdx.y;
    const int t = threadIdx.x;

    const float* s = g_scratch + (size_t)b * 1200;

    if (t < 400) {
        int i = t / NN, k = t - i * NN;
        float pv = s[t], qv = s[400 + t], mv = s[800 + t];
        sPd[i * 21 + k] = pv;
        sPT[k * 24 + i] = pv;
        sQd[i * 21 + k] = qv;
        sQT[k * 24 + i] = qv;
        sMnD[i * 21 + k] = mv;
    }
    __syncthreads();

    if (t < 500) {
        const int x0 = t / 100;
        const int cm = t - x0 * 100;
        const int q  = cm / 5;
        const int y0 = (cm - q * 5) * 4;

        const float4 pt = *reinterpret_cast<const float4*>(sPT + q * 24 + y0);
        int   xs[4];
        float c2[4];
        int   dxv[4];
        #pragma unroll
        for (int j = 0; j < 4; j++) {
            xs[j]  = x0 + 5 * j;
            c2[j]  = sQd[xs[j] * 21 + q];
            dxv[j] = xs[j] - y0;
        }

        float4* ob = reinterpret_cast<float4*>(out) + (size_t)b * 40000 + cm;

        #pragma unroll 2
        for (int pp = 0; pp < 10; pp++) {
            const int p = h * 10 + pp;
            const float4 qc = *reinterpret_cast<const float4*>(sQT + p * 24 + y0);
            const float bx = pt.x + qc.x, by = pt.y + qc.y;
            const float bz = pt.z + qc.z, bw = pt.w + qc.w;
            float4* obp = ob + p * 2000;

            if (q != p) {
                #pragma unroll
                for (int j = 0; j < 4; j++) {
                    const int x = xs[j];
                    const float c1 = sPd[x * 21 + p] + c2[j];
                    float4 v = make_float4(c1 + bx, c1 + by, c1 + bz, c1 + bw);
                    const int dx = dxv[j];
                    if (dx == 0) v.x = 0.f;
                    else if (dx == 1) v.y = 0.f;
                    else if (dx == 2) v.z = 0.f;
                    else if (dx == 3) v.w = 0.f;
                    __stcs(&obp[x * 100], v);
                }
            } else {
                #pragma unroll
                for (int j = 0; j < 4; j++) {
                    const int x = xs[j];
                    float4 v = make_float4(0.f, 0.f, 0.f, 0.f);
                    const float mn = sMnD[x * 21 + p];
                    const int dx = dxv[j];
                    if (dx == 0) v.x = mn;
                    else if (dx == 1) v.y = mn;
                    else if (dx == 2) v.z = mn;
                    else if (dx == 3) v.w = mn;
                    __stcs(&obp[x * 100], v);
                }
            }
        }
    }
}

// ----------------------------------------------------------------- launch ---
extern "C" void kernel_launch(void* const* d_in, const int* in_sizes, int n_in,
                              void* d_out, int out_size)
{
    const float* Fs[4] = {nullptr, nullptr, nullptr, nullptr};
    const float* Ls[2] = {nullptr, nullptr};
    int nf = 0, nl = 0;
    for (int i = 0; i < n_in; i++) {
        if (in_sizes[i] == NB * NN * DD) {
            if (nf < 4) Fs[nf++] = (const float*)d_in[i];
        } else if (in_sizes[i] == DD * DD) {
            if (nl < 2) Ls[nl++] = (const float*)d_in[i];
        }
    }

    const int pq_smem = 3 * NN * STRD * (int)sizeof(float);
    cudaFuncSetAttribute(pq_kernel,
                         cudaFuncAttributeMaxDynamicSharedMemorySize, pq_smem);

    const int prep_threads = MB16 * KB16 * 32 + NB16 * KB16 * 32;  // 180224
    prep_kernel<<<prep_threads / 256, 256>>>(Fs[0], Ls[0], Ls[1]);
    gemm_kernel<<<dim3(8, 40), 256>>>();
    pq_kernel<<<NB, 256, pq_smem>>>(Fs[1], Fs[2], Fs[3]);
    write_kernel<<<dim3(2, NB), 512>>>((float*)d_out);
    (void)out_size;
}